// round 1
// baseline (speedup 1.0000x reference)
#include <cuda_runtime.h>
#include <math.h>

#define B_ 2048
#define D_ 512
#define T_ 16
#define H_ 1024
#define K_ 50
#define NSWEEP 9

// ------------------- device scratch (no allocations allowed) -------------------
__device__ float g_s[B_ * H_];      // (1 - tanh^2(z)) * W2  [B, H]
__device__ float g_grad[B_ * D_];   // grad_x                [B, D]
__device__ float g_d2[B_ * B_];     // pairwise sq distances [B, B]
__device__ float g_sq[B_];          // row squared norms
__device__ int   g_ni[B_ * K_];     // kNN indices           [B, K]
__device__ float g_res[B_];         // per-batch result

// ------------------- squared norms -------------------
__global__ __launch_bounds__(256) void k_sq(const float* __restrict__ p) {
  int w = (blockIdx.x * 256 + threadIdx.x) >> 5;
  int lane = threadIdx.x & 31;
  const float* row = p + w * D_;
  float s = 0.f;
  for (int d = lane; d < D_; d += 32) { float v = row[d]; s += v * v; }
#pragma unroll
  for (int o = 16; o > 0; o >>= 1) s += __shfl_xor_sync(0xffffffffu, s, o);
  if (lane == 0) g_sq[w] = s;
}

// ------------------- GEMM 1: z = [x|t] @ W1 + b1 ; s = (1-tanh^2 z) * W2 -------------------
__global__ __launch_bounds__(256) void k_fwd(const float* __restrict__ xin,
                                             const float* __restrict__ tin,
                                             const float* __restrict__ W1,
                                             const float* __restrict__ b1,
                                             const float* __restrict__ W2) {
  __shared__ __align__(16) float As[16][68];
  __shared__ __align__(16) float Bs[16][68];
  const int tid = threadIdx.x, tx = tid & 15, ty = tid >> 4;
  const int n0 = blockIdx.x * 64, m0 = blockIdx.y * 64;
  float acc[16];
#pragma unroll
  for (int i = 0; i < 16; i++) acc[i] = 0.f;
  for (int k0 = 0; k0 < 528; k0 += 16) {
#pragma unroll
    for (int i = 0; i < 4; i++) {
      int e = tid + i * 256;
      int kk = e & 15, mm = e >> 4;
      int kc = k0 + kk;
      As[kk][mm] = (kc < 512) ? xin[(m0 + mm) * 512 + kc]
                              : tin[(m0 + mm) * 16 + (kc - 512)];
      int nn = e & 63, kb = e >> 6;
      Bs[kb][nn] = W1[(k0 + kb) * 1024 + n0 + nn];
    }
    __syncthreads();
#pragma unroll
    for (int kk = 0; kk < 16; kk++) {
      float4 a4 = *(const float4*)&As[kk][ty * 4];
      float4 b4 = *(const float4*)&Bs[kk][tx * 4];
      float av[4] = {a4.x, a4.y, a4.z, a4.w};
      float bv[4] = {b4.x, b4.y, b4.z, b4.w};
#pragma unroll
      for (int i = 0; i < 4; i++)
#pragma unroll
        for (int j = 0; j < 4; j++) acc[i * 4 + j] += av[i] * bv[j];
    }
    __syncthreads();
  }
#pragma unroll
  for (int i = 0; i < 4; i++) {
    int m = m0 + ty * 4 + i;
    float o[4];
#pragma unroll
    for (int j = 0; j < 4; j++) {
      int n = n0 + tx * 4 + j;
      float z = acc[i * 4 + j] + b1[n];
      float h = tanhf(z);
      o[j] = (1.f - h * h) * W2[n];
    }
    *(float4*)&g_s[m * 1024 + n0 + tx * 4] = make_float4(o[0], o[1], o[2], o[3]);
  }
}

// ------------------- GEMM 2: grad = s @ W1[:512]^T -------------------
__global__ __launch_bounds__(256) void k_grad(const float* __restrict__ W1) {
  __shared__ __align__(16) float As[16][68];
  __shared__ __align__(16) float Bs[16][68];
  const int tid = threadIdx.x, tx = tid & 15, ty = tid >> 4;
  const int n0 = blockIdx.x * 64, m0 = blockIdx.y * 64;
  float acc[16];
#pragma unroll
  for (int i = 0; i < 16; i++) acc[i] = 0.f;
  for (int k0 = 0; k0 < 1024; k0 += 16) {
#pragma unroll
    for (int i = 0; i < 4; i++) {
      int e = tid + i * 256;
      int kk = e & 15, mm = e >> 4;
      As[kk][mm] = g_s[(m0 + mm) * 1024 + k0 + kk];
      Bs[kk][mm] = W1[(n0 + mm) * 1024 + k0 + kk];  // B[k][n] = W1[n][k]
    }
    __syncthreads();
#pragma unroll
    for (int kk = 0; kk < 16; kk++) {
      float4 a4 = *(const float4*)&As[kk][ty * 4];
      float4 b4 = *(const float4*)&Bs[kk][tx * 4];
      float av[4] = {a4.x, a4.y, a4.z, a4.w};
      float bv[4] = {b4.x, b4.y, b4.z, b4.w};
#pragma unroll
      for (int i = 0; i < 4; i++)
#pragma unroll
        for (int j = 0; j < 4; j++) acc[i * 4 + j] += av[i] * bv[j];
    }
    __syncthreads();
  }
#pragma unroll
  for (int i = 0; i < 4; i++) {
    int m = m0 + ty * 4 + i;
    *(float4*)&g_grad[m * 512 + n0 + tx * 4] =
        make_float4(acc[i * 4 + 0], acc[i * 4 + 1], acc[i * 4 + 2], acc[i * 4 + 3]);
  }
}

// ------------------- GEMM 3: d2[i][j] = sq[i] + sq[j] - 2 * p_i . p_j -------------------
__global__ __launch_bounds__(256) void k_d2(const float* __restrict__ p) {
  __shared__ __align__(16) float As[16][68];
  __shared__ __align__(16) float Bs[16][68];
  const int tid = threadIdx.x, tx = tid & 15, ty = tid >> 4;
  const int n0 = blockIdx.x * 64, m0 = blockIdx.y * 64;
  float acc[16];
#pragma unroll
  for (int i = 0; i < 16; i++) acc[i] = 0.f;
  for (int k0 = 0; k0 < 512; k0 += 16) {
#pragma unroll
    for (int i = 0; i < 4; i++) {
      int e = tid + i * 256;
      int kk = e & 15, mm = e >> 4;
      As[kk][mm] = p[(m0 + mm) * 512 + k0 + kk];
      Bs[kk][mm] = p[(n0 + mm) * 512 + k0 + kk];
    }
    __syncthreads();
#pragma unroll
    for (int kk = 0; kk < 16; kk++) {
      float4 a4 = *(const float4*)&As[kk][ty * 4];
      float4 b4 = *(const float4*)&Bs[kk][tx * 4];
      float av[4] = {a4.x, a4.y, a4.z, a4.w};
      float bv[4] = {b4.x, b4.y, b4.z, b4.w};
#pragma unroll
      for (int i = 0; i < 4; i++)
#pragma unroll
        for (int j = 0; j < 4; j++) acc[i * 4 + j] += av[i] * bv[j];
    }
    __syncthreads();
  }
#pragma unroll
  for (int i = 0; i < 4; i++) {
    int m = m0 + ty * 4 + i;
    float sm = g_sq[m];
    float o[4];
#pragma unroll
    for (int j = 0; j < 4; j++) {
      int n = n0 + tx * 4 + j;
      o[j] = sm + g_sq[n] - 2.f * acc[i * 4 + j];
    }
    *(float4*)&g_d2[m * 2048 + n0 + tx * 4] = make_float4(o[0], o[1], o[2], o[3]);
  }
}

// ------------------- top-K via bitonic sort of one row -------------------
__global__ __launch_bounds__(256) void k_topk() {
  __shared__ float key[2048];
  __shared__ int   val[2048];
  const int row = blockIdx.x, tid = threadIdx.x;
  for (int e = tid; e < 2048; e += 256) { key[e] = g_d2[row * 2048 + e]; val[e] = e; }
  __syncthreads();
  for (int k = 2; k <= 2048; k <<= 1) {
    for (int j = k >> 1; j > 0; j >>= 1) {
      for (int e = tid; e < 2048; e += 256) {
        int ixj = e ^ j;
        if (ixj > e) {
          bool up = ((e & k) == 0);
          float ka = key[e], kb = key[ixj];
          if ((ka > kb) == up) {
            key[e] = kb; key[ixj] = ka;
            int va = val[e]; val[e] = val[ixj]; val[ixj] = va;
          }
        }
      }
      __syncthreads();
    }
  }
  if (tid < K_) g_ni[row * K_ + tid] = val[tid];
}

// ------------------- per-batch: Gram + w + Jacobi eigensolve + top-16 projection -------------------
__device__ __forceinline__ void accum_tile(float* acc, const float (*Cs)[132], int r0, int q0) {
#pragma unroll 4
  for (int d = 0; d < 128; d += 4) {
    float4 ar[4], br[4];
#pragma unroll
    for (int i = 0; i < 4; i++) ar[i] = *(const float4*)&Cs[r0 + i][d];
#pragma unroll
    for (int j = 0; j < 4; j++) br[j] = *(const float4*)&Cs[q0 + j][d];
#pragma unroll
    for (int i = 0; i < 4; i++)
#pragma unroll
      for (int j = 0; j < 4; j++)
        acc[i * 4 + j] += ar[i].x * br[j].x + ar[i].y * br[j].y +
                          ar[i].z * br[j].z + ar[i].w * br[j].w;
  }
}

__global__ __launch_bounds__(128) void k_batch(const float* __restrict__ pert) {
  __shared__ __align__(16) float Cs[52][132];   // neighbor chunk (rows 50,51 zero pad)
  __shared__ float Gm[50][53];                  // Gram matrix (pad 53: conflict-free cols)
  __shared__ float wv[50];
  __shared__ float gs[128];
  __shared__ int   nidx[50];
  __shared__ float cc[25], sh[25];
  __shared__ int   pr[25], qr[25];

  const int b = blockIdx.x, tid = threadIdx.x;
  if (tid < 50) nidx[tid] = g_ni[b * K_ + tid];
  for (int dd = tid; dd < 132; dd += 128) { Cs[50][dd] = 0.f; Cs[51][dd] = 0.f; }

  float wreg = 0.f;
  float acc0[16], acc1[16];
#pragma unroll
  for (int i = 0; i < 16; i++) { acc0[i] = 0.f; acc1[i] = 0.f; }
  const int tile0 = tid, tile1 = tid + 128;  // 169 tiles of 4x4 covering 52x52
  __syncthreads();

  for (int c = 0; c < 4; c++) {
    // gather chunk: 50 rows x 128 cols (float4, coalesced per row)
    for (int e = tid; e < 1600; e += 128) {
      int row = e >> 5;
      int c4 = (e & 31) << 2;
      float4 v = *(const float4*)&pert[nidx[row] * 512 + c * 128 + c4];
      *(float4*)&Cs[row][c4] = v;
    }
    gs[tid] = g_grad[b * 512 + c * 128 + tid];
    __syncthreads();
    // mean over K per column, then center
    {
      int d = tid;
      float sm = 0.f;
#pragma unroll 10
      for (int k = 0; k < 50; k++) sm += Cs[k][d];
      sm *= (1.0f / 50.0f);
      for (int k = 0; k < 50; k++) Cs[k][d] -= sm;
    }
    __syncthreads();
    // w += C_chunk @ g_chunk
    if (tid < 50) {
      const float4* rp = (const float4*)&Cs[tid][0];
      const float4* gp = (const float4*)&gs[0];
      float s = 0.f;
#pragma unroll 8
      for (int d4 = 0; d4 < 32; d4++) {
        float4 a = rp[d4], g4 = gp[d4];
        s += a.x * g4.x + a.y * g4.y + a.z * g4.z + a.w * g4.w;
      }
      wreg += s;
    }
    // G += C_chunk C_chunk^T  (4x4 register tiles)
    accum_tile(acc0, Cs, (tile0 / 13) * 4, (tile0 % 13) * 4);
    if (tile1 < 169) accum_tile(acc1, Cs, (tile1 / 13) * 4, (tile1 % 13) * 4);
    __syncthreads();
  }
  // write G
  {
    int r0 = (tile0 / 13) * 4, q0 = (tile0 % 13) * 4;
#pragma unroll
    for (int i = 0; i < 4; i++)
#pragma unroll
      for (int j = 0; j < 4; j++) {
        int r = r0 + i, q = q0 + j;
        if (r < 50 && q < 50) Gm[r][q] = acc0[i * 4 + j];
      }
    if (tile1 < 169) {
      int r1 = (tile1 / 13) * 4, q1 = (tile1 % 13) * 4;
#pragma unroll
      for (int i = 0; i < 4; i++)
#pragma unroll
        for (int j = 0; j < 4; j++) {
          int r = r1 + i, q = q1 + j;
          if (r < 50 && q < 50) Gm[r][q] = acc1[i * 4 + j];
        }
    }
  }
  if (tid < 50) wv[tid] = wreg;
  __syncthreads();

  // parallel cyclic Jacobi: 25 disjoint rotations per round, 49 rounds per sweep
  for (int sw = 0; sw < NSWEEP; sw++) {
    for (int r = 0; r < 49; r++) {
      if (tid < 25) {
        int p, q;
        if (tid == 0) { p = 49; q = r % 49; }
        else {
          p = (r + tid) % 49;
          int qq = (r - tid) % 49; if (qq < 0) qq += 49;
          q = qq;
        }
        float app = Gm[p][p], aqq = Gm[q][q], apq = Gm[p][q];
        float c = 1.f, s = 0.f;
        if (apq != 0.0f) {
          float tau = (aqq - app) / (2.0f * apq);
          float tt = copysignf(1.0f, tau) / (fabsf(tau) + sqrtf(1.0f + tau * tau));
          c = 1.0f / sqrtf(1.0f + tt * tt);
          s = tt * c;
        }
        pr[tid] = p; qr[tid] = q; cc[tid] = c; sh[tid] = s;
      }
      __syncthreads();
      // rows: A <- J^T A
      for (int task = tid; task < 1250; task += 128) {
        int j = task % 50, pi = task / 50;
        int p = pr[pi], q = qr[pi];
        float c = cc[pi], s = sh[pi];
        float ap = Gm[p][j], aq = Gm[q][j];
        Gm[p][j] = c * ap - s * aq;
        Gm[q][j] = s * ap + c * aq;
      }
      if (tid < 25) {  // w' <- J^T w'
        int p = pr[tid], q = qr[tid];
        float c = cc[tid], s = sh[tid];
        float wp = wv[p], wq = wv[q];
        wv[p] = c * wp - s * wq;
        wv[q] = s * wp + c * wq;
      }
      __syncthreads();
      // cols: A <- A J
      for (int task = tid; task < 1250; task += 128) {
        int i2 = task % 50, pi = task / 50;
        int p = pr[pi], q = qr[pi];
        float c = cc[pi], s = sh[pi];
        float aip = Gm[i2][p], aiq = Gm[i2][q];
        Gm[i2][p] = c * aip - s * aiq;
        Gm[i2][q] = s * aip + c * aiq;
      }
      __syncthreads();
    }
  }

  if (tid == 0) {
    float lam[50];
    for (int i = 0; i < 50; i++) lam[i] = Gm[i][i];
    float res = 0.f;
    for (int m = 0; m < 16; m++) {
      int bi = 0; float bv = -1e30f;
      for (int i = 0; i < 50; i++)
        if (lam[i] > bv) { bv = lam[i]; bi = i; }
      res += wv[bi] * wv[bi] / bv;
      lam[bi] = -1e30f;
    }
    g_res[b] = res;
  }
}

// ------------------- deterministic reduce -------------------
__global__ __launch_bounds__(256) void k_reduce(float* __restrict__ out) {
  __shared__ float sm[256];
  int tid = threadIdx.x;
  float s = 0.f;
  for (int i = tid; i < B_; i += 256) s += g_res[i];
  sm[tid] = s;
  __syncthreads();
  for (int o = 128; o > 0; o >>= 1) {
    if (tid < o) sm[tid] += sm[tid + o];
    __syncthreads();
  }
  if (tid == 0) out[0] = sm[0] / (float)B_;
}

// ------------------- launch -------------------
extern "C" void kernel_launch(void* const* d_in, const int* in_sizes, int n_in,
                              void* d_out, int out_size) {
  const float* x    = (const float*)d_in[0];
  const float* t    = (const float*)d_in[1];
  const float* pert = (const float*)d_in[2];
  const float* W1   = (const float*)d_in[3];
  const float* b1   = (const float*)d_in[4];
  const float* W2   = (const float*)d_in[5];
  // d_in[6] = b2: gradient w.r.t. x does not depend on it
  float* out = (float*)d_out;

  k_sq  <<<B_ / 8, 256>>>(pert);                       // 2048 warps
  k_fwd <<<dim3(H_ / 64, B_ / 64), 256>>>(x, t, W1, b1, W2);
  k_grad<<<dim3(D_ / 64, B_ / 64), 256>>>(W1);
  k_d2  <<<dim3(B_ / 64, B_ / 64), 256>>>(pert);
  k_topk<<<B_, 256>>>();
  k_batch<<<B_, 128>>>(pert);
  k_reduce<<<1, 256>>>(out);
}

// round 2
// speedup vs baseline: 1.3405x; 1.3405x over previous
#include <cuda_runtime.h>
#include <math.h>

#define B_ 2048
#define D_ 512
#define T_ 16
#define H_ 1024
#define K_ 50
#define NSWEEP 6

// ------------------- device scratch (no allocations allowed) -------------------
__device__ float g_s[B_ * H_];      // (1 - tanh^2(z)) * W2  [B, H]
__device__ float g_grad[B_ * D_];   // grad_x                [B, D]
__device__ float g_d2[B_ * B_];     // pairwise sq distances [B, B]
__device__ float g_sq[B_];          // row squared norms
__device__ int   g_ni[B_ * K_];     // kNN indices           [B, K]
__device__ float g_res[B_];         // per-batch result

// ------------------- squared norms -------------------
__global__ __launch_bounds__(256) void k_sq(const float* __restrict__ p) {
  int w = (blockIdx.x * 256 + threadIdx.x) >> 5;
  int lane = threadIdx.x & 31;
  const float* row = p + w * D_;
  float s = 0.f;
  for (int d = lane; d < D_; d += 32) { float v = row[d]; s += v * v; }
#pragma unroll
  for (int o = 16; o > 0; o >>= 1) s += __shfl_xor_sync(0xffffffffu, s, o);
  if (lane == 0) g_sq[w] = s;
}

// ------------------- GEMM 1: z = [x|t] @ W1 + b1 ; s = (1-tanh^2 z) * W2 -------------------
__global__ __launch_bounds__(256) void k_fwd(const float* __restrict__ xin,
                                             const float* __restrict__ tin,
                                             const float* __restrict__ W1,
                                             const float* __restrict__ b1,
                                             const float* __restrict__ W2) {
  __shared__ __align__(16) float As[16][68];
  __shared__ __align__(16) float Bs[16][68];
  const int tid = threadIdx.x, tx = tid & 15, ty = tid >> 4;
  const int n0 = blockIdx.x * 64, m0 = blockIdx.y * 64;
  float acc[16];
#pragma unroll
  for (int i = 0; i < 16; i++) acc[i] = 0.f;
  for (int k0 = 0; k0 < 528; k0 += 16) {
#pragma unroll
    for (int i = 0; i < 4; i++) {
      int e = tid + i * 256;
      int kk = e & 15, mm = e >> 4;
      int kc = k0 + kk;
      As[kk][mm] = (kc < 512) ? xin[(m0 + mm) * 512 + kc]
                              : tin[(m0 + mm) * 16 + (kc - 512)];
      int nn = e & 63, kb = e >> 6;
      Bs[kb][nn] = W1[(k0 + kb) * 1024 + n0 + nn];
    }
    __syncthreads();
#pragma unroll
    for (int kk = 0; kk < 16; kk++) {
      float4 a4 = *(const float4*)&As[kk][ty * 4];
      float4 b4 = *(const float4*)&Bs[kk][tx * 4];
      float av[4] = {a4.x, a4.y, a4.z, a4.w};
      float bv[4] = {b4.x, b4.y, b4.z, b4.w};
#pragma unroll
      for (int i = 0; i < 4; i++)
#pragma unroll
        for (int j = 0; j < 4; j++) acc[i * 4 + j] += av[i] * bv[j];
    }
    __syncthreads();
  }
#pragma unroll
  for (int i = 0; i < 4; i++) {
    int m = m0 + ty * 4 + i;
    float o[4];
#pragma unroll
    for (int j = 0; j < 4; j++) {
      int n = n0 + tx * 4 + j;
      float z = acc[i * 4 + j] + b1[n];
      float h = tanhf(z);
      o[j] = (1.f - h * h) * W2[n];
    }
    *(float4*)&g_s[m * 1024 + n0 + tx * 4] = make_float4(o[0], o[1], o[2], o[3]);
  }
}

// ------------------- GEMM 2: grad = s @ W1[:512]^T -------------------
__global__ __launch_bounds__(256) void k_grad(const float* __restrict__ W1) {
  __shared__ __align__(16) float As[16][68];
  __shared__ __align__(16) float Bs[16][68];
  const int tid = threadIdx.x, tx = tid & 15, ty = tid >> 4;
  const int n0 = blockIdx.x * 64, m0 = blockIdx.y * 64;
  float acc[16];
#pragma unroll
  for (int i = 0; i < 16; i++) acc[i] = 0.f;
  for (int k0 = 0; k0 < 1024; k0 += 16) {
#pragma unroll
    for (int i = 0; i < 4; i++) {
      int e = tid + i * 256;
      int kk = e & 15, mm = e >> 4;
      As[kk][mm] = g_s[(m0 + mm) * 1024 + k0 + kk];
      Bs[kk][mm] = W1[(n0 + mm) * 1024 + k0 + kk];  // B[k][n] = W1[n][k]
    }
    __syncthreads();
#pragma unroll
    for (int kk = 0; kk < 16; kk++) {
      float4 a4 = *(const float4*)&As[kk][ty * 4];
      float4 b4 = *(const float4*)&Bs[kk][tx * 4];
      float av[4] = {a4.x, a4.y, a4.z, a4.w};
      float bv[4] = {b4.x, b4.y, b4.z, b4.w};
#pragma unroll
      for (int i = 0; i < 4; i++)
#pragma unroll
        for (int j = 0; j < 4; j++) acc[i * 4 + j] += av[i] * bv[j];
    }
    __syncthreads();
  }
#pragma unroll
  for (int i = 0; i < 4; i++) {
    int m = m0 + ty * 4 + i;
    *(float4*)&g_grad[m * 512 + n0 + tx * 4] =
        make_float4(acc[i * 4 + 0], acc[i * 4 + 1], acc[i * 4 + 2], acc[i * 4 + 3]);
  }
}

// ------------------- GEMM 3: d2[i][j] = sq[i] + sq[j] - 2 * p_i . p_j -------------------
__global__ __launch_bounds__(256) void k_d2(const float* __restrict__ p) {
  __shared__ __align__(16) float As[16][68];
  __shared__ __align__(16) float Bs[16][68];
  const int tid = threadIdx.x, tx = tid & 15, ty = tid >> 4;
  const int n0 = blockIdx.x * 64, m0 = blockIdx.y * 64;
  float acc[16];
#pragma unroll
  for (int i = 0; i < 16; i++) acc[i] = 0.f;
  for (int k0 = 0; k0 < 512; k0 += 16) {
#pragma unroll
    for (int i = 0; i < 4; i++) {
      int e = tid + i * 256;
      int kk = e & 15, mm = e >> 4;
      As[kk][mm] = p[(m0 + mm) * 512 + k0 + kk];
      Bs[kk][mm] = p[(n0 + mm) * 512 + k0 + kk];
    }
    __syncthreads();
#pragma unroll
    for (int kk = 0; kk < 16; kk++) {
      float4 a4 = *(const float4*)&As[kk][ty * 4];
      float4 b4 = *(const float4*)&Bs[kk][tx * 4];
      float av[4] = {a4.x, a4.y, a4.z, a4.w};
      float bv[4] = {b4.x, b4.y, b4.z, b4.w};
#pragma unroll
      for (int i = 0; i < 4; i++)
#pragma unroll
        for (int j = 0; j < 4; j++) acc[i * 4 + j] += av[i] * bv[j];
    }
    __syncthreads();
  }
#pragma unroll
  for (int i = 0; i < 4; i++) {
    int m = m0 + ty * 4 + i;
    float sm = g_sq[m];
    float o[4];
#pragma unroll
    for (int j = 0; j < 4; j++) {
      int n = n0 + tx * 4 + j;
      o[j] = sm + g_sq[n] - 2.f * acc[i * 4 + j];
    }
    *(float4*)&g_d2[m * 2048 + n0 + tx * 4] = make_float4(o[0], o[1], o[2], o[3]);
  }
}

// ------------------- top-K via bitonic sort of one row -------------------
__global__ __launch_bounds__(256) void k_topk() {
  __shared__ float key[2048];
  __shared__ int   val[2048];
  const int row = blockIdx.x, tid = threadIdx.x;
  for (int e = tid; e < 2048; e += 256) { key[e] = g_d2[row * 2048 + e]; val[e] = e; }
  __syncthreads();
  for (int k = 2; k <= 2048; k <<= 1) {
    for (int j = k >> 1; j > 0; j >>= 1) {
      for (int e = tid; e < 2048; e += 256) {
        int ixj = e ^ j;
        if (ixj > e) {
          bool up = ((e & k) == 0);
          float ka = key[e], kb = key[ixj];
          if ((ka > kb) == up) {
            key[e] = kb; key[ixj] = ka;
            int va = val[e]; val[e] = val[ixj]; val[ixj] = va;
          }
        }
      }
      __syncthreads();
    }
  }
  if (tid < K_) g_ni[row * K_ + tid] = val[tid];
}

// ------------------- per-batch: Gram + w + Jacobi eigensolve + top-16 projection -------------------
__device__ __forceinline__ void accum_tile(float* acc, const float (*Cs)[132], int r0, int q0) {
#pragma unroll 4
  for (int d = 0; d < 128; d += 4) {
    float4 ar[4], br[4];
#pragma unroll
    for (int i = 0; i < 4; i++) ar[i] = *(const float4*)&Cs[r0 + i][d];
#pragma unroll
    for (int j = 0; j < 4; j++) br[j] = *(const float4*)&Cs[q0 + j][d];
#pragma unroll
    for (int i = 0; i < 4; i++)
#pragma unroll
      for (int j = 0; j < 4; j++)
        acc[i * 4 + j] += ar[i].x * br[j].x + ar[i].y * br[j].y +
                          ar[i].z * br[j].z + ar[i].w * br[j].w;
  }
}

__global__ __launch_bounds__(128) void k_batch(const float* __restrict__ pert) {
  __shared__ __align__(16) float Cs[52][132];   // neighbor chunk (rows 50,51 zero pad)
  __shared__ float Gm[50][53];                  // Gram matrix (pitch 53: conflict-free)
  __shared__ float wv[50];
  __shared__ float gs[128];
  __shared__ int   nidx[50];
  __shared__ float cc[25], sh[25];
  __shared__ int   pr[25], qr[25];
  __shared__ float contrib[16];

  const int b = blockIdx.x, tid = threadIdx.x;
  if (tid < 50) nidx[tid] = g_ni[b * K_ + tid];
  for (int dd = tid; dd < 132; dd += 128) { Cs[50][dd] = 0.f; Cs[51][dd] = 0.f; }

  float wreg = 0.f;
  float acc0[16], acc1[16];
#pragma unroll
  for (int i = 0; i < 16; i++) { acc0[i] = 0.f; acc1[i] = 0.f; }
  const int tile0 = tid, tile1 = tid + 128;  // 169 tiles of 4x4 covering 52x52
  __syncthreads();

  for (int c = 0; c < 4; c++) {
    // gather chunk: 50 rows x 128 cols (float4, coalesced per row)
    for (int e = tid; e < 1600; e += 128) {
      int row = e >> 5;
      int c4 = (e & 31) << 2;
      float4 v = *(const float4*)&pert[nidx[row] * 512 + c * 128 + c4];
      *(float4*)&Cs[row][c4] = v;
    }
    gs[tid] = g_grad[b * 512 + c * 128 + tid];
    __syncthreads();
    // mean over K per column, then center
    {
      int d = tid;
      float sm = 0.f;
#pragma unroll 10
      for (int k = 0; k < 50; k++) sm += Cs[k][d];
      sm *= (1.0f / 50.0f);
      for (int k = 0; k < 50; k++) Cs[k][d] -= sm;
    }
    __syncthreads();
    // w += C_chunk @ g_chunk
    if (tid < 50) {
      const float4* rp = (const float4*)&Cs[tid][0];
      const float4* gp = (const float4*)&gs[0];
      float s = 0.f;
#pragma unroll 8
      for (int d4 = 0; d4 < 32; d4++) {
        float4 a = rp[d4], g4 = gp[d4];
        s += a.x * g4.x + a.y * g4.y + a.z * g4.z + a.w * g4.w;
      }
      wreg += s;
    }
    // G += C_chunk C_chunk^T  (4x4 register tiles)
    accum_tile(acc0, Cs, (tile0 / 13) * 4, (tile0 % 13) * 4);
    if (tile1 < 169) accum_tile(acc1, Cs, (tile1 / 13) * 4, (tile1 % 13) * 4);
    __syncthreads();
  }
  // write G
  {
    int r0 = (tile0 / 13) * 4, q0 = (tile0 % 13) * 4;
#pragma unroll
    for (int i = 0; i < 4; i++)
#pragma unroll
      for (int j = 0; j < 4; j++) {
        int r = r0 + i, q = q0 + j;
        if (r < 50 && q < 50) Gm[r][q] = acc0[i * 4 + j];
      }
    if (tile1 < 169) {
      int r1 = (tile1 / 13) * 4, q1 = (tile1 % 13) * 4;
#pragma unroll
      for (int i = 0; i < 4; i++)
#pragma unroll
        for (int j = 0; j < 4; j++) {
          int r = r1 + i, q = q1 + j;
          if (r < 50 && q < 50) Gm[r][q] = acc1[i * 4 + j];
        }
    }
  }
  if (tid < 50) wv[tid] = wreg;

  // Fixed mapping for Jacobi phases, computed ONCE: pair pi, column offset c0.
  const int pi = tid / 5;          // 0..24 for tid<125
  const int c0 = tid - pi * 5;     // 0..4
  const bool act = (tid < 125);
  __syncthreads();

  // parallel cyclic Jacobi: 25 disjoint rotations per round, 49 rounds per sweep
  for (int sw = 0; sw < NSWEEP; sw++) {
    for (int r = 0; r < 49; r++) {
      if (tid < 25) {
        int p, q;
        if (tid == 0) { p = 49; q = r % 49; }
        else {
          p = (r + tid) % 49;
          int qq = (r - tid) % 49; if (qq < 0) qq += 49;
          q = qq;
        }
        float app = Gm[p][p], aqq = Gm[q][q], apq = Gm[p][q];
        float c = 1.f, s = 0.f;
        if (apq != 0.0f) {
          float tau = (aqq - app) / (2.0f * apq);
          float tt = copysignf(1.0f, tau) / (fabsf(tau) + sqrtf(1.0f + tau * tau));
          c = 1.0f / sqrtf(1.0f + tt * tt);
          s = tt * c;
        }
        pr[tid] = p; qr[tid] = q; cc[tid] = c; sh[tid] = s;
      }
      __syncthreads();
      // rows: A <- J^T A   (each thread: pair pi, columns c0, c0+5, ..., c0+45)
      if (act) {
        const int p = pr[pi], q = qr[pi];
        const float c = cc[pi], s = sh[pi];
        float* __restrict__ rowp = &Gm[p][0];
        float* __restrict__ rowq = &Gm[q][0];
#pragma unroll
        for (int k = 0; k < 10; k++) {
          int j = c0 + 5 * k;
          float ap = rowp[j], aq = rowq[j];
          rowp[j] = c * ap - s * aq;
          rowq[j] = s * ap + c * aq;
        }
      }
      __syncthreads();
      // cols: A <- A J ; plus w rotation by the c0==0 thread of each pair
      if (act) {
        const int p = pr[pi], q = qr[pi];
        const float c = cc[pi], s = sh[pi];
#pragma unroll
        for (int k = 0; k < 10; k++) {
          int i2 = c0 + 5 * k;
          float aip = Gm[i2][p], aiq = Gm[i2][q];
          Gm[i2][p] = c * aip - s * aiq;
          Gm[i2][q] = s * aip + c * aiq;
        }
        if (c0 == 0) {
          float wp = wv[p], wq = wv[q];
          wv[p] = c * wp - s * wq;
          wv[q] = s * wp + c * wq;
        }
      }
      __syncthreads();
    }
  }

  // parallel rank-based top-16 selection (deterministic, tie-break by index)
  if (tid < 50) {
    float li = Gm[tid][tid];
    int rank = 0;
#pragma unroll 10
    for (int j = 0; j < 50; j++) {
      float lj = Gm[j][j];
      rank += (lj > li) || (lj == li && j < tid);
    }
    if (rank < 16) contrib[rank] = wv[tid] * wv[tid] / li;
  }
  __syncthreads();
  if (tid == 0) {
    float r = 0.f;
#pragma unroll
    for (int m = 0; m < 16; m++) r += contrib[m];
    g_res[b] = r;
  }
}

// ------------------- deterministic reduce -------------------
__global__ __launch_bounds__(256) void k_reduce(float* __restrict__ out) {
  __shared__ float sm[256];
  int tid = threadIdx.x;
  float s = 0.f;
  for (int i = tid; i < B_; i += 256) s += g_res[i];
  sm[tid] = s;
  __syncthreads();
  for (int o = 128; o > 0; o >>= 1) {
    if (tid < o) sm[tid] += sm[tid + o];
    __syncthreads();
  }
  if (tid == 0) out[0] = sm[0] / (float)B_;
}

// ------------------- launch -------------------
extern "C" void kernel_launch(void* const* d_in, const int* in_sizes, int n_in,
                              void* d_out, int out_size) {
  const float* x    = (const float*)d_in[0];
  const float* t    = (const float*)d_in[1];
  const float* pert = (const float*)d_in[2];
  const float* W1   = (const float*)d_in[3];
  const float* b1   = (const float*)d_in[4];
  const float* W2   = (const float*)d_in[5];
  // d_in[6] = b2: gradient w.r.t. x does not depend on it
  float* out = (float*)d_out;

  k_sq  <<<B_ / 8, 256>>>(pert);
  k_fwd <<<dim3(H_ / 64, B_ / 64), 256>>>(x, t, W1, b1, W2);
  k_grad<<<dim3(D_ / 64, B_ / 64), 256>>>(W1);
  k_d2  <<<dim3(B_ / 64, B_ / 64), 256>>>(pert);
  k_topk<<<B_, 256>>>();
  k_batch<<<B_, 128>>>(pert);
  k_reduce<<<1, 256>>>(out);
}